// round 16
// baseline (speedup 1.0000x reference)
#include <cuda_runtime.h>

#define RNUM 2000
#define DDIM 128
#define HNUM 4
#define CAPZ 512
#define CAPE 64
#define SPLIT 4
#define SCB 4096

// ---- cp.async helpers ----
__device__ __forceinline__ void cpa16(unsigned smem, const void* g) {
    asm volatile("cp.async.cg.shared.global [%0], [%1], 16;" :: "r"(smem), "l"(g)
                 : "memory");
}
#define CPA_COMMIT() asm volatile("cp.async.commit_group;" ::: "memory")
#define CPA_WAIT2()  asm volatile("cp.async.wait_group 2;" ::: "memory")
#define CPA_WAIT1()  asm volatile("cp.async.wait_group 1;" ::: "memory")
#define CPA_WAIT0()  asm volatile("cp.async.wait_group 0;" ::: "memory")

// ---- scratch (static device globals; no allocation) ----
__device__ float g_q[DDIM];
__device__ float g_a[HNUM * DDIM];
__device__ float g_c[HNUM];
__device__ int   g_count[RNUM];
__device__ int   g_ecount[RNUM];
__device__ int   g_done[RNUM];
__device__ int   g_sorted[RNUM * CAPZ];               // row indices bucketed by zone
__device__ int   g_esrc[RNUM * CAPE];                 // edge sources bucketed by dst
__device__ float g_pxbar[RNUM * SPLIT * HNUM * DDIM]; // per-(region,sub) weighted sums
__device__ float g_pden[RNUM * SPLIT * HNUM];         // per-(region,sub) denominators
__device__ float g_hh[RNUM * DDIM];

// ---- prep: block 0 computes q, a = (q^T Wk)*log2e/sqrt(D), c; block 1 zeroes ----
__global__ void prep_kernel(const float* __restrict__ S, const float* __restrict__ Wq,
                            const float* __restrict__ bq, const float* __restrict__ Wk,
                            const float* __restrict__ bk) {
    if (blockIdx.x == 1) {
        for (int i = threadIdx.x; i < RNUM; i += blockDim.x) {
            g_count[i] = 0;
            g_ecount[i] = 0;
            g_done[i] = 0;
        }
        return;
    }
    __shared__ float sS[DDIM];
    __shared__ float sq[DDIM];
    int i = threadIdx.x;  // 128 threads
    sS[i] = S[i];
    __syncthreads();
    float qi = bq[i];
    for (int j = 0; j < DDIM; j++) qi = fmaf(sS[j], Wq[i * DDIM + j], qi);
    sq[i] = qi;
    g_q[i] = qi;
    __syncthreads();
    // fold 1/sqrt(128) AND log2(e) into the score coefficients -> bare exp2 later
    const float invs = 0.08838834764831845f * 1.4426950408889634f;
    for (int h = 0; h < HNUM; h++) {
        float s = 0.f;
        for (int d = 0; d < 32; d++)
            s = fmaf(sq[h * 32 + d], Wk[(h * 32 + d) * DDIM + i], s);
        g_a[h * DDIM + i] = s * invs;
    }
    if (i < HNUM) {
        float s = 0.f;
        for (int d = 0; d < 32; d++) s = fmaf(sq[i * 32 + d], bk[i * 32 + d], s);
        g_c[i] = s * invs;
    }
}

// ---- merged scatter: blocks [0, ZB) do zone rows; blocks [ZB, ZB+8) do edges ----
__global__ __launch_bounds__(256) void scatter_kernel(const int* __restrict__ zone,
                                                      const int* __restrict__ adj,
                                                      int N, int E, int ZB) {
    int tid = threadIdx.x;
    if ((int)blockIdx.x >= ZB) {
        // edge scatter: bucket sources by dst
        int eb = blockIdx.x - ZB;
        for (int u = eb * 256 + tid; u < E; u += 8 * 256) {
            int src = adj[u];
            int dst = adj[E + u];
            int p = atomicAdd(&g_ecount[dst], 1);
            if (p < CAPE) g_esrc[dst * CAPE + p] = src;
        }
        return;
    }
    __shared__ int hist[RNUM];
    int base = blockIdx.x * SCB;
    int nit = N - base;
    if (nit > SCB) nit = SCB;
    for (int z = tid; z < RNUM; z += 256) hist[z] = 0;
    __syncthreads();
    int nq = nit >> 2;
    for (int qi = tid; qi < nq; qi += 256) {
        int4 z = __ldg((const int4*)(zone + base) + qi);
        atomicAdd(&hist[z.x], 1);
        atomicAdd(&hist[z.y], 1);
        atomicAdd(&hist[z.z], 1);
        atomicAdd(&hist[z.w], 1);
    }
    for (int i = (nq << 2) + tid; i < nit; i += 256)
        atomicAdd(&hist[zone[base + i]], 1);
    __syncthreads();
    for (int z = tid; z < RNUM; z += 256) {
        int c = hist[z];
        hist[z] = (c > 0) ? atomicAdd(&g_count[z], c) : 0;
    }
    __syncthreads();
    for (int qi = tid; qi < nq; qi += 256) {
        int4 z = __ldg((const int4*)(zone + base) + qi);
        int b = base + (qi << 2);
        int p0 = atomicAdd(&hist[z.x], 1);
        int p1 = atomicAdd(&hist[z.y], 1);
        int p2 = atomicAdd(&hist[z.z], 1);
        int p3 = atomicAdd(&hist[z.w], 1);
        if (p0 < CAPZ) g_sorted[z.x * CAPZ + p0] = b;
        if (p1 < CAPZ) g_sorted[z.y * CAPZ + p1] = b + 1;
        if (p2 < CAPZ) g_sorted[z.z * CAPZ + p2] = b + 2;
        if (p3 < CAPZ) g_sorted[z.w * CAPZ + p3] = b + 3;
    }
    for (int i = (nq << 2) + tid; i < nit; i += 256) {
        int z = zone[base + i];
        int p = atomicAdd(&hist[z], 1);
        if (p < CAPZ) g_sorted[z * CAPZ + p] = base + i;
    }
}

// ---- 8-row coalesced GEMV with 9-shuffle joint fold ----
__device__ __forceinline__ float gemv8_fold(const float4* __restrict__ Wb,
                                            float4 xv, int lane) {
    const unsigned F = 0xffffffffu;
    float d[8];
#pragma unroll
    for (int k = 0; k < 8; k++) {
        float4 wv = __ldg(Wb + k * 32 + lane);
        float t = wv.x * xv.x;
        t = fmaf(wv.y, xv.y, t);
        t = fmaf(wv.z, xv.z, t);
        t = fmaf(wv.w, xv.w, t);
        d[k] = t;
    }
    bool b4 = lane & 16, b3 = lane & 8, b2 = lane & 4;
    float v0 = (b4 ? d[1] : d[0]) + __shfl_xor_sync(F, b4 ? d[0] : d[1], 16);
    float v1 = (b4 ? d[3] : d[2]) + __shfl_xor_sync(F, b4 ? d[2] : d[3], 16);
    float v2 = (b4 ? d[5] : d[4]) + __shfl_xor_sync(F, b4 ? d[4] : d[5], 16);
    float v3 = (b4 ? d[7] : d[6]) + __shfl_xor_sync(F, b4 ? d[6] : d[7], 16);
    float u0 = (b3 ? v1 : v0) + __shfl_xor_sync(F, b3 ? v0 : v1, 8);
    float u1 = (b3 ? v3 : v2) + __shfl_xor_sync(F, b3 ? v2 : v3, 8);
    float s  = (b2 ? u1 : u0) + __shfl_xor_sync(F, b2 ? u0 : u1, 4);
    s += __shfl_xor_sync(F, s, 2);
    s += __shfl_xor_sync(F, s, 1);
    return s;
}

// ---- shared-memory layout: x staging buffers (streaming) UNION reduce state ----
struct RedSM {
    float swacc[4][HNUM][DDIM];  // 8 KB
    float swden[4][HNUM];
    float sxbar[HNUM][DDIM];     // 2 KB
    float sden[HNUM];
    float sO[DDIM];
    float sO2[DDIM];
};
union PartialSM {
    float xbuf[4][3][4][DDIM];   // 24 KB: [warp][stage][row][dim]
    RedSM red;
};

// ---- partial + fused finalize. 128 threads; blockIdx = region*SPLIT + sub.
// Gathered x rows staged through smem via TRIPLE-buffered cp.async.cg.
__global__ __launch_bounds__(128, 8) void partial_kernel(
    const float* __restrict__ x,
    const float* __restrict__ Wv, const float* __restrict__ bv,
    const float* __restrict__ Wo, const float* __restrict__ bo,
    const float* __restrict__ Wg) {
    __shared__ PartialSM sm;
    __shared__ int s_last;

    const unsigned F = 0xffffffffu;
    int rb = blockIdx.x;
    int r = rb >> 2, sub = rb & 3;
    int tid = threadIdx.x;
    int w = tid >> 5, lane = tid & 31;
    int lh = lane & 3;

    int cnt = g_count[r];
    if (cnt > CAPZ) cnt = CAPZ;
    int q4 = (((cnt + 3) >> 2) + 3) & ~3;  // rows per sub, rounded to multiple of 4
    int begin = sub * q4;
    if (begin > cnt) begin = cnt;
    int end = begin + q4;
    if (end > cnt) end = cnt;
    const int* lst = g_sorted + r * CAPZ;

    float areg[HNUM][4];
#pragma unroll
    for (int h = 0; h < HNUM; h++) {
        float4 a4 = __ldg((const float4*)(g_a + h * DDIM) + lane);
        areg[h][0] = a4.x; areg[h][1] = a4.y; areg[h][2] = a4.z; areg[h][3] = a4.w;
    }
    float cper = g_c[lh];

    float acc[4][4];
    float den[4] = {0.f, 0.f, 0.f, 0.f};
#pragma unroll
    for (int k = 0; k < 4; k++)
#pragma unroll
        for (int j = 0; j < 4; j++) acc[k][j] = 0.f;

    // one row's full update; `valid` is warp-uniform (compile-folds on fast path)
    auto dorow = [&](const float4& xv, bool valid) {
        float p0 = areg[0][0] * xv.x;
        p0 = fmaf(areg[0][1], xv.y, p0);
        p0 = fmaf(areg[0][2], xv.z, p0);
        p0 = fmaf(areg[0][3], xv.w, p0);
        float p1 = areg[1][0] * xv.x;
        p1 = fmaf(areg[1][1], xv.y, p1);
        p1 = fmaf(areg[1][2], xv.z, p1);
        p1 = fmaf(areg[1][3], xv.w, p1);
        float p2 = areg[2][0] * xv.x;
        p2 = fmaf(areg[2][1], xv.y, p2);
        p2 = fmaf(areg[2][2], xv.z, p2);
        p2 = fmaf(areg[2][3], xv.w, p2);
        float p3 = areg[3][0] * xv.x;
        p3 = fmaf(areg[3][1], xv.y, p3);
        p3 = fmaf(areg[3][2], xv.z, p3);
        p3 = fmaf(areg[3][3], xv.w, p3);
        bool b0 = lane & 1;
        bool b1 = lane & 2;
        float rA = (b0 ? p1 : p0) + __shfl_xor_sync(F, b0 ? p0 : p1, 1);
        float rB = (b0 ? p3 : p2) + __shfl_xor_sync(F, b0 ? p2 : p3, 1);
        float rr = (b1 ? rB : rA) + __shfl_xor_sync(F, b1 ? rA : rB, 2);
        rr += __shfl_xor_sync(F, rr, 4);
        rr += __shfl_xor_sync(F, rr, 8);
        rr += __shfl_xor_sync(F, rr, 16);
        float e0 = valid ? exp2f(rr + cper) : 0.f;    // coeffs pre-scaled by log2e
        float e1 = __shfl_xor_sync(F, e0, 1);
        float e2 = __shfl_xor_sync(F, e0, 2);
        float e3 = __shfl_xor_sync(F, e0, 3);
        den[0] += e0; den[1] += e1; den[2] += e2; den[3] += e3;
        acc[0][0] = fmaf(e0, xv.x, acc[0][0]);
        acc[0][1] = fmaf(e0, xv.y, acc[0][1]);
        acc[0][2] = fmaf(e0, xv.z, acc[0][2]);
        acc[0][3] = fmaf(e0, xv.w, acc[0][3]);
        acc[1][0] = fmaf(e1, xv.x, acc[1][0]);
        acc[1][1] = fmaf(e1, xv.y, acc[1][1]);
        acc[1][2] = fmaf(e1, xv.z, acc[1][2]);
        acc[1][3] = fmaf(e1, xv.w, acc[1][3]);
        acc[2][0] = fmaf(e2, xv.x, acc[2][0]);
        acc[2][1] = fmaf(e2, xv.y, acc[2][1]);
        acc[2][2] = fmaf(e2, xv.z, acc[2][2]);
        acc[2][3] = fmaf(e2, xv.w, acc[2][3]);
        acc[3][0] = fmaf(e3, xv.x, acc[3][0]);
        acc[3][1] = fmaf(e3, xv.y, acc[3][1]);
        acc[3][2] = fmaf(e3, xv.z, acc[3][2]);
        acc[3][3] = fmaf(e3, xv.w, acc[3][3]);
    };

    // issue one group's cp.async copies (4 rows, this lane's 16B of each)
    auto issue_grp = [&](int b, int stage) {
        unsigned sb = (unsigned)__cvta_generic_to_shared(&sm.xbuf[w][stage][0][0]) +
                      (unsigned)(lane * 16);
        if (b + 4 <= end) {
            int4 id = *(const int4*)(lst + b);
            cpa16(sb + 0 * 512, x + (size_t)id.x * DDIM + lane * 4);
            cpa16(sb + 1 * 512, x + (size_t)id.y * DDIM + lane * 4);
            cpa16(sb + 2 * 512, x + (size_t)id.z * DDIM + lane * 4);
            cpa16(sb + 3 * 512, x + (size_t)id.w * DDIM + lane * 4);
        } else {
            int last = end - 1;
#pragma unroll
            for (int u = 0; u < 4; u++) {
                int i = b + u;
                if (i > last) i = last;
                cpa16(sb + u * 512, x + (size_t)lst[i] * DDIM + lane * 4);
            }
        }
        CPA_COMMIT();
    };

    int myb = begin + w * 4;
    if (myb < end) {
        issue_grp(myb, 0);
        if (myb + 16 < end) issue_grp(myb + 16, 1);
        int base = myb;
        int stage = 0;
        for (;;) {
            int nb1 = base + 16;
            int nb2 = base + 32;
            bool has1 = nb1 < end;
            bool has2 = nb2 < end;
            if (has2) {
                int st2 = stage + 2;
                if (st2 >= 3) st2 -= 3;
                issue_grp(nb2, st2);
                CPA_WAIT2();
            } else if (has1) {
                CPA_WAIT1();
            } else {
                CPA_WAIT0();
            }
            const float4* rp = (const float4*)&sm.xbuf[w][stage][0][0];
            float4 v0 = rp[lane];
            float4 v1 = rp[32 + lane];
            float4 v2 = rp[64 + lane];
            float4 v3 = rp[96 + lane];
            if (base + 4 <= end) {
                dorow(v0, true);
                dorow(v1, true);
                dorow(v2, true);
                dorow(v3, true);
            } else {
                dorow(v0, base + 0 < end);
                dorow(v1, base + 1 < end);
                dorow(v2, base + 2 < end);
                dorow(v3, base + 3 < end);
            }
            if (!has1) break;
            base = nb1;
            if (++stage == 3) stage = 0;
        }
    }
    // all warps must finish streaming before the union is reused for reduction
    __syncthreads();
    // stage per-warp partials: acc[k] belongs to head lh^k, dims 4*lane..+3
#pragma unroll
    for (int k = 0; k < 4; k++) {
        int h = lh ^ k;
        sm.red.swacc[w][h][lane * 4 + 0] = acc[k][0];
        sm.red.swacc[w][h][lane * 4 + 1] = acc[k][1];
        sm.red.swacc[w][h][lane * 4 + 2] = acc[k][2];
        sm.red.swacc[w][h][lane * 4 + 3] = acc[k][3];
    }
    if (lane < 4) {
#pragma unroll
        for (int k = 0; k < 4; k++) sm.red.swden[w][lh ^ k] = den[k];
    }
    __syncthreads();
    // block-reduce across 4 warps and write partials (coalesced)
    for (int p = tid; p < HNUM * DDIM; p += 128) {
        int h = p >> 7, j = p & 127;
        g_pxbar[(size_t)rb * (HNUM * DDIM) + p] =
            sm.red.swacc[0][h][j] + sm.red.swacc[1][h][j] +
            sm.red.swacc[2][h][j] + sm.red.swacc[3][h][j];
    }
    if (tid < HNUM)
        g_pden[rb * HNUM + tid] =
            sm.red.swden[0][tid] + sm.red.swden[1][tid] +
            sm.red.swden[2][tid] + sm.red.swden[3][tid];

    // ---- last-done sub-block runs finalize for this region ----
    __threadfence();
    __syncthreads();
    if (tid == 0) s_last = (atomicAdd(&g_done[r], 1) == SPLIT - 1);
    __syncthreads();
    if (!s_last) return;
    __threadfence();

    // reduce SPLIT partials (just written -> L2-hot); bypass L1
    for (int p = tid; p < HNUM * DDIM; p += 128) {
        size_t b = (size_t)r * SPLIT * (HNUM * DDIM);
        float s = __ldcg(&g_pxbar[b + p]) + __ldcg(&g_pxbar[b + 512 + p]) +
                  __ldcg(&g_pxbar[b + 1024 + p]) + __ldcg(&g_pxbar[b + 1536 + p]);
        sm.red.sxbar[p >> 7][p & 127] = s;
    }
    if (tid < HNUM) {
        int b = r * SPLIT * HNUM;
        sm.red.sden[tid] = __ldcg(&g_pden[b + tid]) + __ldcg(&g_pden[b + 4 + tid]) +
                           __ldcg(&g_pden[b + 8 + tid]) + __ldcg(&g_pden[b + 12 + tid]);
    }
    __syncthreads();

    int rowsel = ((lane >> 4) & 1) | (((lane >> 3) & 1) << 1) | (((lane >> 2) & 1) << 2);
    bool isw = (lane & 3) == 0;
    // ---- stage 1: O = q + (Wv . xbar[head]) / den + bv ; warp w == head w
    {
        float dn = sm.red.sden[w];
        float inv = (dn > 0.f) ? (1.f / dn) : 0.f;
        float4 xv = ((const float4*)&sm.red.sxbar[w][0])[lane];
        const float4* Wb = (const float4*)(Wv + (w * 32) * DDIM);
#pragma unroll
        for (int t = 0; t < 4; t++) {
            float s = gemv8_fold(Wb + t * 8 * 32, xv, lane);
            if (isw) {
                int row = w * 32 + t * 8 + rowsel;
                float pooled = (dn > 0.f) ? (s * inv + bv[row]) : 0.f;
                sm.red.sO[row] = g_q[row] + pooled;
            }
        }
    }
    __syncthreads();
    // ---- stage 2: O2 = O + relu(Wo . O + bo)
    {
        float4 xv = ((const float4*)sm.red.sO)[lane];
        const float4* Wb = (const float4*)(Wo + (w * 32) * DDIM);
#pragma unroll
        for (int t = 0; t < 4; t++) {
            float s = gemv8_fold(Wb + t * 8 * 32, xv, lane);
            if (isw) {
                int row = w * 32 + t * 8 + rowsel;
                sm.red.sO2[row] = sm.red.sO[row] + fmaxf(s + bo[row], 0.f);
            }
        }
    }
    __syncthreads();
    // ---- stage 3: hh = Wg . O2
    {
        float4 xv = ((const float4*)sm.red.sO2)[lane];
        const float4* Wb = (const float4*)(Wg + (w * 32) * DDIM);
#pragma unroll
        for (int t = 0; t < 4; t++) {
            float s = gemv8_fold(Wb + t * 8 * 32, xv, lane);
            if (isw) {
                int row = w * 32 + t * 8 + rowsel;
                g_hh[r * DDIM + row] = s;
            }
        }
    }
}

// ---- GCN gather (bucketed by dst) + self loop + bias + PReLU ----
// 4 independent accumulator chains to expose load-level parallelism.
__global__ void gather_kernel(const float* __restrict__ bg,
                              const float* __restrict__ prelu_w,
                              float* __restrict__ out) {
    int r = blockIdx.x, i = threadIdx.x;
    int ec = g_ecount[r];
    int ecl = (ec > CAPE) ? CAPE : ec;
    float degr = (float)(ec + 1);
    float disr = rsqrtf(degr);
    float a0 = g_hh[r * DDIM + i] / degr;  // self-loop: dis_r^2
    float a1 = 0.f, a2 = 0.f, a3 = 0.f;
    const int* es = g_esrc + r * CAPE;
    int k = 0;
    for (; k + 4 <= ecl; k += 4) {
        int s0 = es[k], s1 = es[k + 1], s2 = es[k + 2], s3 = es[k + 3];
        float n0 = disr * rsqrtf((float)(g_ecount[s0] + 1));
        float n1 = disr * rsqrtf((float)(g_ecount[s1] + 1));
        float n2 = disr * rsqrtf((float)(g_ecount[s2] + 1));
        float n3 = disr * rsqrtf((float)(g_ecount[s3] + 1));
        a0 = fmaf(n0, g_hh[s0 * DDIM + i], a0);
        a1 = fmaf(n1, g_hh[s1 * DDIM + i], a1);
        a2 = fmaf(n2, g_hh[s2 * DDIM + i], a2);
        a3 = fmaf(n3, g_hh[s3 * DDIM + i], a3);
    }
    for (; k < ecl; k++) {
        int src = es[k];
        float nrm = disr * rsqrtf((float)(g_ecount[src] + 1));
        a0 = fmaf(nrm, g_hh[src * DDIM + i], a0);
    }
    float v = (a0 + a1) + (a2 + a3) + bg[i];
    out[r * DDIM + i] = (v > 0.f) ? v : prelu_w[i] * v;
}

extern "C" void kernel_launch(void* const* d_in, const int* in_sizes, int n_in,
                              void* d_out, int out_size) {
    const float* x    = (const float*)d_in[0];
    const int*   zone = (const int*)d_in[1];
    const int*   adj  = (const int*)d_in[2];
    const float* S    = (const float*)d_in[3];
    const float* Wq   = (const float*)d_in[4];
    const float* bq   = (const float*)d_in[5];
    const float* Wk   = (const float*)d_in[6];
    const float* bk   = (const float*)d_in[7];
    const float* Wv   = (const float*)d_in[8];
    const float* bv   = (const float*)d_in[9];
    const float* Wo   = (const float*)d_in[10];
    const float* bo   = (const float*)d_in[11];
    const float* Wg   = (const float*)d_in[12];
    const float* bg   = (const float*)d_in[13];
    const float* pw   = (const float*)d_in[14];
    int N = in_sizes[0] / DDIM;
    int E = in_sizes[2] / 2;

    prep_kernel<<<2, 128>>>(S, Wq, bq, Wk, bk);
    int ZB = (N + SCB - 1) / SCB;
    scatter_kernel<<<ZB + 8, 256>>>(zone, adj, N, E, ZB);
    partial_kernel<<<RNUM * SPLIT, 128>>>(x, Wv, bv, Wo, bo, Wg);
    gather_kernel<<<RNUM, DDIM>>>(bg, pw, (float*)d_out);
}